// round 6
// baseline (speedup 1.0000x reference)
#include <cuda_runtime.h>

#define NN 100000
#define NE 3200000
#define DF 128
#define H1 32
#define H2 16
#define NC 8

// ---- scratch (device globals; no allocs allowed) ----
__device__ __align__(16) float g_g1[NN * H1];    // g1 = (x@W1)*dinv
__device__ __align__(16) float g_agg1[NN * H1];  // scatter accumulator 1
__device__ __align__(16) float g_g2[NN * H2];    // g2 = (relu1@W2)*dinv
__device__ __align__(16) float g_agg2[NN * H2];  // scatter accumulator 2
__device__ float g_dinv[NN];
__device__ int   g_deg[NN];
__device__ __align__(8) int2 g_edge[NE];         // (src, dst) int32

// ---- K0: deg = 1 (self loop) ----
__global__ void k_init_deg() {
    int i = blockIdx.x * blockDim.x + threadIdx.x;
    if (i < NN) g_deg[i] = 1;
}

// ---- K1: pack edges -> int2, degree histogram ----
__global__ void k_edges(const int* __restrict__ ei) {
    int e = blockIdx.x * blockDim.x + threadIdx.x;
    if (e < NE) {
        int s = ei[e];
        int d = ei[NE + e];
        g_edge[e] = make_int2(s, d);
        atomicAdd(&g_deg[d], 1);
    }
}

// ---- K2: dinv = rsqrt(deg) ----
__global__ void k_dinv() {
    int i = blockIdx.x * blockDim.x + threadIdx.x;
    if (i < NN) g_dinv[i] = rsqrtf((float)g_deg[i]);
}

// ---- K3: g1 = (x @ W1) * dinv ; agg1 = g1 (self-loop term) ----
// 8 warps/block, one node per warp, W1 (128x32) staged in shared.
__global__ void k_gemm1(const float* __restrict__ x, const float* __restrict__ W1) {
    __shared__ float sW[DF * H1];      // 16 KB
    __shared__ float sx[8][DF];        // 4 KB
    int tid = threadIdx.x;
    for (int i = tid; i < DF * H1; i += 256) sW[i] = W1[i];
    __syncthreads();
    int warp = tid >> 5, lane = tid & 31;
    int node = blockIdx.x * 8 + warp;  // NN % 8 == 0, always in range
    // cooperative row load: 32 lanes x float4 = 128 floats
    float4 v = ((const float4*)(x + (size_t)node * DF))[lane];
    ((float4*)sx[warp])[lane] = v;
    __syncwarp();
    float acc = 0.f;
#pragma unroll
    for (int k = 0; k < DF; k++)
        acc = fmaf(sx[warp][k], sW[k * H1 + lane], acc);
    float g = acc * g_dinv[node];
    g_g1[node * H1 + lane]  = g;
    g_agg1[node * H1 + lane] = g;
}

// ---- K4: scatter pass 1: agg1[dst] += g1[src]  (warp per edge, 32 feats) ----
__global__ void k_scatter1() {
    long long gid = (long long)blockIdx.x * blockDim.x + threadIdx.x;
    int e = (int)(gid >> 5);
    if (e >= NE) return;
    int lane = (int)(gid & 31);
    int2 sd = g_edge[e];
    float v = g_g1[sd.x * H1 + lane];
    atomicAdd(&g_agg1[sd.y * H1 + lane], v);
}

// ---- K5: relu(dinv*agg1 + b1) @ W2 * dinv -> g2 ; agg2 = g2 ----
__global__ void k_mid(const float* __restrict__ b1, const float* __restrict__ W2) {
    __shared__ float sW[H1 * H2];      // 2 KB
    __shared__ float su[8][H1];
    int tid = threadIdx.x;
    for (int i = tid; i < H1 * H2; i += 256) sW[i] = W2[i];
    __syncthreads();
    int warp = tid >> 5, lane = tid & 31;
    int node = blockIdx.x * 8 + warp;
    float dinv = g_dinv[node];
    float u = fmaxf(fmaf(g_agg1[node * H1 + lane], dinv, b1[lane]), 0.f);
    su[warp][lane] = u;
    __syncwarp();
    if (lane < H2) {
        float acc = 0.f;
#pragma unroll
        for (int k = 0; k < H1; k++)
            acc = fmaf(su[warp][k], sW[k * H2 + lane], acc);
        float g = acc * dinv;
        g_g2[node * H2 + lane]  = g;
        g_agg2[node * H2 + lane] = g;
    }
}

// ---- K6: scatter pass 2: agg2[dst] += g2[src]  (16 lanes per edge) ----
__global__ void k_scatter2() {
    long long gid = (long long)blockIdx.x * blockDim.x + threadIdx.x;
    int e = (int)(gid >> 4);
    if (e >= NE) return;
    int lane = (int)(gid & 15);
    int2 sd = g_edge[e];
    float v = g_g2[sd.x * H2 + lane];
    atomicAdd(&g_agg2[sd.y * H2 + lane], v);
}

// ---- K7: relu(dinv*agg2 + b2) @ Wc + bc -> log_softmax -> out ----
__global__ void k_final(const float* __restrict__ b2, const float* __restrict__ Wc,
                        const float* __restrict__ bc, float* __restrict__ out) {
    int node = blockIdx.x * blockDim.x + threadIdx.x;
    if (node >= NN) return;
    float dinv = g_dinv[node];
    float u[H2];
    const float4* a = (const float4*)(g_agg2 + (size_t)node * H2);
#pragma unroll
    for (int q = 0; q < 4; q++) {
        float4 v = a[q];
        u[4 * q + 0] = v.x; u[4 * q + 1] = v.y;
        u[4 * q + 2] = v.z; u[4 * q + 3] = v.w;
    }
#pragma unroll
    for (int k = 0; k < H2; k++)
        u[k] = fmaxf(fmaf(u[k], dinv, __ldg(&b2[k])), 0.f);
    float l[NC];
#pragma unroll
    for (int j = 0; j < NC; j++) l[j] = __ldg(&bc[j]);
#pragma unroll
    for (int k = 0; k < H2; k++) {
        float uk = u[k];
#pragma unroll
        for (int j = 0; j < NC; j++)
            l[j] = fmaf(uk, __ldg(&Wc[k * NC + j]), l[j]);
    }
    float m = l[0];
#pragma unroll
    for (int j = 1; j < NC; j++) m = fmaxf(m, l[j]);
    float s = 0.f;
#pragma unroll
    for (int j = 0; j < NC; j++) s += expf(l[j] - m);
    float lse = m + logf(s);
    float4* o = (float4*)(out + (size_t)node * NC);
    o[0] = make_float4(l[0] - lse, l[1] - lse, l[2] - lse, l[3] - lse);
    o[1] = make_float4(l[4] - lse, l[5] - lse, l[6] - lse, l[7] - lse);
}

extern "C" void kernel_launch(void* const* d_in, const int* in_sizes, int n_in,
                              void* d_out, int out_size) {
    (void)out_size;
    // Map inputs by element count (all sizes distinct) — robust to ordering.
    const float* x  = nullptr; const int* ei = nullptr;
    const float* W1 = nullptr; const float* b1 = nullptr;
    const float* W2 = nullptr; const float* b2 = nullptr;
    const float* Wc = nullptr; const float* bc = nullptr;
    for (int i = 0; i < n_in; i++) {
        switch (in_sizes[i]) {
            case NN * DF:    x  = (const float*)d_in[i]; break;  // 12,800,000
            case 2 * NE:     ei = (const int*)d_in[i];   break;  //  6,400,000
            case DF * H1:    W1 = (const float*)d_in[i]; break;  //      4,096
            case H1 * H2:    W2 = (const float*)d_in[i]; break;  //        512
            case H2 * NC:    Wc = (const float*)d_in[i]; break;  //        128
            case H1:         b1 = (const float*)d_in[i]; break;  //         32
            case H2:         b2 = (const float*)d_in[i]; break;  //         16
            case NC:         bc = (const float*)d_in[i]; break;  //          8
            default: break;
        }
    }
    float* out = (float*)d_out;

    k_init_deg<<<(NN + 255) / 256, 256>>>();
    k_edges<<<(NE + 255) / 256, 256>>>(ei);
    k_dinv<<<(NN + 255) / 256, 256>>>();
    k_gemm1<<<NN / 8, 256>>>(x, W1);                 // 12500 blocks
    k_scatter1<<<(NE * 32) / 256, 256>>>();          // 400000 blocks
    k_mid<<<NN / 8, 256>>>(b1, W2);
    k_scatter2<<<(NE * 16) / 256, 256>>>();          // 200000 blocks
    k_final<<<(NN + 255) / 256, 256>>>(b2, Wc, bc, out);
}

// round 7
// speedup vs baseline: 2.4005x; 2.4005x over previous
#include <cuda_runtime.h>

#define NN 100000
#define NE 3200000
#define DF 128
#define H1 32
#define H2 16
#define NC 8
#define NBLK 391          // ceil(NN/256)

// ---- scratch (device globals; no allocs allowed) ----
__device__ __align__(16) float g_g1[NN * H1];    // g1 = (x@W1)*dinv
__device__ __align__(16) float g_g2[NN * H2];    // g2 = (relu1@W2)*dinv
__device__ __align__(16) float g_agg2[NN * H2];  // aggregated layer-2 messages
__device__ float g_dinv[NN];
__device__ int   g_cnt[NN];                      // in-degree (no self loop)
__device__ int   g_off[NN + 1];                  // CSR offsets
__device__ int   g_cur[NN];                      // placement cursors
__device__ int   g_bsum[NBLK + 1];
__device__ int   g_bpref[NBLK + 1];
__device__ int   g_csr[NE];                      // src ids grouped by dst
__device__ __align__(8) int2 g_edge[NE];         // packed (src,dst)

// ---- K0: cnt = 0 ----
__global__ void k_init() {
    int i = blockIdx.x * blockDim.x + threadIdx.x;
    if (i < NN) g_cnt[i] = 0;
}

// ---- K1: pack edges -> int2, degree histogram ----
__global__ void k_edges(const int* __restrict__ ei) {
    int e = blockIdx.x * blockDim.x + threadIdx.x;
    if (e < NE) {
        int s = ei[e];
        int d = ei[NE + e];
        g_edge[e] = make_int2(s, d);
        atomicAdd(&g_cnt[d], 1);
    }
}

// ---- K2: dinv = rsqrt(deg+1)  (+1 = self loop) ----
__global__ void k_dinv() {
    int i = blockIdx.x * blockDim.x + threadIdx.x;
    if (i < NN) g_dinv[i] = rsqrtf((float)(g_cnt[i] + 1));
}

// ---- K3a: per-block exclusive scan of cnt ----
__global__ void k_scan_block() {
    __shared__ int swarp[8];
    __shared__ int soff[8];
    int t = threadIdx.x;
    int i = blockIdx.x * 256 + t;
    int v = (i < NN) ? g_cnt[i] : 0;
    int incl = v;
#pragma unroll
    for (int d = 1; d < 32; d <<= 1) {
        int n = __shfl_up_sync(~0u, incl, d);
        if ((t & 31) >= d) incl += n;
    }
    if ((t & 31) == 31) swarp[t >> 5] = incl;
    __syncthreads();
    if (t == 0) {
        int run = 0;
#pragma unroll
        for (int w = 0; w < 8; w++) { soff[w] = run; run += swarp[w]; }
        g_bsum[blockIdx.x] = run;
    }
    __syncthreads();
    if (i < NN) g_off[i] = incl - v + soff[t >> 5];
}

// ---- K3b: scan the 391 block sums (one block) ----
__global__ void k_scan_top() {
    __shared__ int sv[512];
    int t = threadIdx.x;
    int v = (t < NBLK) ? g_bsum[t] : 0;
    sv[t] = v;
    __syncthreads();
    for (int d = 1; d < 512; d <<= 1) {
        int n = (t >= d) ? sv[t - d] : 0;
        __syncthreads();
        sv[t] += n;
        __syncthreads();
    }
    if (t < NBLK) g_bpref[t] = sv[t] - v;   // exclusive
}

// ---- K3c: add block prefixes; init cursors; off[NN]=NE ----
__global__ void k_scan_add() {
    int i = blockIdx.x * blockDim.x + threadIdx.x;
    if (i < NN) {
        int o = g_off[i] + g_bpref[i >> 8];
        g_off[i] = o;
        g_cur[i] = o;
    }
    if (i == 0) g_off[NN] = NE;
}

// ---- K4: place edges into CSR slots (int atomics on spread cursors) ----
__global__ void k_place() {
    int e = blockIdx.x * blockDim.x + threadIdx.x;
    if (e < NE) {
        int2 sd = g_edge[e];
        int pos = atomicAdd(&g_cur[sd.y], 1);
        g_csr[pos] = sd.x;
    }
}

// ---- K5: g1 = (x @ W1) * dinv  — 4-node register tile, float4 LDS ----
__global__ void k_gemm1(const float* __restrict__ x, const float* __restrict__ W1) {
    __shared__ float sWt[H1][DF + 4];   // W1 transposed: [col][k], pad keeps rows 16B-aligned
    __shared__ float sx[32][DF + 4];    // 32 node rows per block
    int tid = threadIdx.x;
    for (int i = tid; i < DF * H1; i += 256) {
        int k = i >> 5, j = i & 31;
        sWt[j][k] = W1[i];
    }
    int node0 = blockIdx.x * 32;
    for (int i = tid; i < 32 * (DF / 4); i += 256) {
        int r = i >> 5, c = i & 31;
        ((float4*)&sx[r][0])[c] =
            ((const float4*)(x + (size_t)(node0 + r) * DF))[c];
    }
    __syncthreads();
    int warp = tid >> 5, lane = tid & 31;
    int nb = warp * 4;
    float acc0 = 0.f, acc1 = 0.f, acc2 = 0.f, acc3 = 0.f;
    const float4* wt = (const float4*)&sWt[lane][0];
    const float4* x0 = (const float4*)&sx[nb + 0][0];
    const float4* x1 = (const float4*)&sx[nb + 1][0];
    const float4* x2 = (const float4*)&sx[nb + 2][0];
    const float4* x3 = (const float4*)&sx[nb + 3][0];
#pragma unroll 8
    for (int q = 0; q < DF / 4; q++) {
        float4 w = wt[q];
        float4 a = x0[q], b = x1[q], c = x2[q], d = x3[q];
        acc0 += a.x * w.x + a.y * w.y + a.z * w.z + a.w * w.w;
        acc1 += b.x * w.x + b.y * w.y + b.z * w.z + b.w * w.w;
        acc2 += c.x * w.x + c.y * w.y + c.z * w.z + c.w * w.w;
        acc3 += d.x * w.x + d.y * w.y + d.z * w.z + d.w * w.w;
    }
    int n = node0 + nb;
    g_g1[(n + 0) * H1 + lane] = acc0 * g_dinv[n + 0];
    g_g1[(n + 1) * H1 + lane] = acc1 * g_dinv[n + 1];
    g_g1[(n + 2) * H1 + lane] = acc2 * g_dinv[n + 2];
    g_g1[(n + 3) * H1 + lane] = acc3 * g_dinv[n + 3];
}

// ---- K6: gather layer-1 messages + relu + W2 matvec + dinv -> g2 ----
// warp per node; lane = feature (32)
__global__ void k_gather_mid(const float* __restrict__ b1, const float* __restrict__ W2) {
    __shared__ float sW2[H1 * H2];
    __shared__ float su[8][H1 + 1];
    int tid = threadIdx.x;
    for (int i = tid; i < H1 * H2; i += 256) sW2[i] = W2[i];
    __syncthreads();
    int warp = tid >> 5, lane = tid & 31;
    int node = blockIdx.x * 8 + warp;       // NN % 8 == 0
    float acc = g_g1[node * H1 + lane];     // self-loop term
    int s = g_off[node], t = g_off[node + 1];
    for (int e = s; e < t; e++) {
        int src = __ldg(&g_csr[e]);
        acc += g_g1[src * H1 + lane];
    }
    float dinv = g_dinv[node];
    float u = fmaxf(fmaf(acc, dinv, b1[lane]), 0.f);
    su[warp][lane] = u;
    __syncwarp();
    if (lane < H2) {
        float a = 0.f;
#pragma unroll
        for (int k = 0; k < H1; k++)
            a = fmaf(su[warp][k], sW2[k * H2 + lane], a);
        g_g2[node * H2 + lane] = a * dinv;
    }
}

// ---- K7: gather layer-2 messages -> agg2 (warp per node, 2 edges/iter) ----
__global__ void k_gather2() {
    int tid = threadIdx.x;
    int warp = tid >> 5, lane = tid & 31;
    int node = blockIdx.x * 8 + warp;
    int half = lane >> 4, f = lane & 15;
    int s = g_off[node], t = g_off[node + 1];
    float acc = 0.f;
    for (int e = s + half; e < t; e += 2) {
        int src = __ldg(&g_csr[e]);
        acc += g_g2[src * H2 + f];
    }
    acc += __shfl_xor_sync(~0u, acc, 16);
    if (half == 0)
        g_agg2[node * H2 + f] = acc + g_g2[node * H2 + f];  // + self loop
}

// ---- K8: relu(dinv*agg2 + b2) @ Wc + bc -> log_softmax -> out ----
__global__ void k_final(const float* __restrict__ b2, const float* __restrict__ Wc,
                        const float* __restrict__ bc, float* __restrict__ out) {
    int node = blockIdx.x * blockDim.x + threadIdx.x;
    if (node >= NN) return;
    float dinv = g_dinv[node];
    float u[H2];
    const float4* a = (const float4*)(g_agg2 + (size_t)node * H2);
#pragma unroll
    for (int q = 0; q < 4; q++) {
        float4 v = a[q];
        u[4 * q + 0] = v.x; u[4 * q + 1] = v.y;
        u[4 * q + 2] = v.z; u[4 * q + 3] = v.w;
    }
#pragma unroll
    for (int k = 0; k < H2; k++)
        u[k] = fmaxf(fmaf(u[k], dinv, __ldg(&b2[k])), 0.f);
    float l[NC];
#pragma unroll
    for (int j = 0; j < NC; j++) l[j] = __ldg(&bc[j]);
#pragma unroll
    for (int k = 0; k < H2; k++) {
        float uk = u[k];
#pragma unroll
        for (int j = 0; j < NC; j++)
            l[j] = fmaf(uk, __ldg(&Wc[k * NC + j]), l[j]);
    }
    float m = l[0];
#pragma unroll
    for (int j = 1; j < NC; j++) m = fmaxf(m, l[j]);
    float sum = 0.f;
#pragma unroll
    for (int j = 0; j < NC; j++) sum += expf(l[j] - m);
    float lse = m + logf(sum);
    float4* o = (float4*)(out + (size_t)node * NC);
    o[0] = make_float4(l[0] - lse, l[1] - lse, l[2] - lse, l[3] - lse);
    o[1] = make_float4(l[4] - lse, l[5] - lse, l[6] - lse, l[7] - lse);
}

extern "C" void kernel_launch(void* const* d_in, const int* in_sizes, int n_in,
                              void* d_out, int out_size) {
    (void)out_size;
    const float* x  = nullptr; const int* ei = nullptr;
    const float* W1 = nullptr; const float* b1 = nullptr;
    const float* W2 = nullptr; const float* b2 = nullptr;
    const float* Wc = nullptr; const float* bc = nullptr;
    for (int i = 0; i < n_in; i++) {
        switch (in_sizes[i]) {
            case NN * DF:    x  = (const float*)d_in[i]; break;  // 12,800,000
            case 2 * NE:     ei = (const int*)d_in[i];   break;  //  6,400,000
            case DF * H1:    W1 = (const float*)d_in[i]; break;  //      4,096
            case H1 * H2:    W2 = (const float*)d_in[i]; break;  //        512
            case H2 * NC:    Wc = (const float*)d_in[i]; break;  //        128
            case H1:         b1 = (const float*)d_in[i]; break;  //         32
            case H2:         b2 = (const float*)d_in[i]; break;  //         16
            case NC:         bc = (const float*)d_in[i]; break;  //          8
            default: break;
        }
    }
    float* out = (float*)d_out;

    k_init<<<NBLK, 256>>>();
    k_edges<<<NE / 256, 256>>>(ei);
    k_dinv<<<NBLK, 256>>>();
    k_scan_block<<<NBLK, 256>>>();
    k_scan_top<<<1, 512>>>();
    k_scan_add<<<NBLK, 256>>>();
    k_place<<<NE / 256, 256>>>();
    k_gemm1<<<NN / 32, 256>>>(x, W1);       // 3125 blocks
    k_gather_mid<<<NN / 8, 256>>>(b1, W2);  // 12500 blocks
    k_gather2<<<NN / 8, 256>>>();
    k_final<<<NBLK, 256>>>(b2, Wc, bc, out);
}

// round 8
// speedup vs baseline: 2.6195x; 1.0912x over previous
#include <cuda_runtime.h>
#include <cuda_fp16.h>

#define NN 100000
#define NE 3200000
#define DF 128
#define H1 32
#define H2 16
#define NC 8
#define NBLK 391          // ceil(NN/256)

// ---- scratch (device globals; no allocs allowed) ----
__device__ __align__(16) __half2 g_g1h[NN * (H1 / 2)]; // g1 = (x@W1)*dinv, fp16
__device__ __align__(16) __half2 g_g2h[NN * (H2 / 2)]; // g2 = (relu1@W2)*dinv, fp16
__device__ __align__(16) float g_agg2[NN * H2];        // aggregated layer-2 (fp32)
__device__ float g_dinv[NN];
__device__ int   g_cnt[NN];                      // in-degree (no self loop)
__device__ int   g_off[NN + 1];                  // CSR offsets
__device__ int   g_cur[NN];                      // placement cursors
__device__ int   g_bsum[NBLK + 1];
__device__ int   g_bpref[NBLK + 1];
__device__ int   g_csr[NE];                      // src ids grouped by dst

// ---- K0: cnt = 0 ----
__global__ void k_init() {
    int i = blockIdx.x * blockDim.x + threadIdx.x;
    if (i < NN) g_cnt[i] = 0;
}

// ---- K1: degree histogram from dst column only ----
__global__ void k_deg(const int* __restrict__ ei) {
    int e = blockIdx.x * blockDim.x + threadIdx.x;
    if (e < NE) atomicAdd(&g_cnt[ei[NE + e]], 1);
}

// ---- K2: dinv = rsqrt(deg+1)  (+1 = self loop) ----
__global__ void k_dinv() {
    int i = blockIdx.x * blockDim.x + threadIdx.x;
    if (i < NN) g_dinv[i] = rsqrtf((float)(g_cnt[i] + 1));
}

// ---- K3a: per-block exclusive scan of cnt ----
__global__ void k_scan_block() {
    __shared__ int swarp[8];
    __shared__ int soff[8];
    int t = threadIdx.x;
    int i = blockIdx.x * 256 + t;
    int v = (i < NN) ? g_cnt[i] : 0;
    int incl = v;
#pragma unroll
    for (int d = 1; d < 32; d <<= 1) {
        int n = __shfl_up_sync(~0u, incl, d);
        if ((t & 31) >= d) incl += n;
    }
    if ((t & 31) == 31) swarp[t >> 5] = incl;
    __syncthreads();
    if (t == 0) {
        int run = 0;
#pragma unroll
        for (int w = 0; w < 8; w++) { soff[w] = run; run += swarp[w]; }
        g_bsum[blockIdx.x] = run;
    }
    __syncthreads();
    if (i < NN) g_off[i] = incl - v + soff[t >> 5];
}

// ---- K3b: scan the 391 block sums (one block) ----
__global__ void k_scan_top() {
    __shared__ int sv[512];
    int t = threadIdx.x;
    int v = (t < NBLK) ? g_bsum[t] : 0;
    sv[t] = v;
    __syncthreads();
    for (int d = 1; d < 512; d <<= 1) {
        int n = (t >= d) ? sv[t - d] : 0;
        __syncthreads();
        sv[t] += n;
        __syncthreads();
    }
    if (t < NBLK) g_bpref[t] = sv[t] - v;   // exclusive
}

// ---- K3c: add block prefixes; init cursors; off[NN]=NE ----
__global__ void k_scan_add() {
    int i = blockIdx.x * blockDim.x + threadIdx.x;
    if (i < NN) {
        int o = g_off[i] + g_bpref[i >> 8];
        g_off[i] = o;
        g_cur[i] = o;
    }
    if (i == 0) g_off[NN] = NE;
}

// ---- K4: place edges into CSR slots directly from input columns ----
__global__ void k_place(const int* __restrict__ ei) {
    int e = blockIdx.x * blockDim.x + threadIdx.x;
    if (e < NE) {
        int s = ei[e];
        int d = ei[NE + e];
        int pos = atomicAdd(&g_cur[d], 1);
        g_csr[pos] = s;
    }
}

// ---- K5: g1 = (x @ W1) * dinv  -> fp16 packed ----
__global__ void k_gemm1(const float* __restrict__ x, const float* __restrict__ W1) {
    __shared__ float sWt[H1][DF + 4];   // W1 transposed: [col][k]
    __shared__ float sx[32][DF + 4];    // 32 node rows per block
    int tid = threadIdx.x;
    for (int i = tid; i < DF * H1; i += 256) {
        int k = i >> 5, j = i & 31;
        sWt[j][k] = W1[i];
    }
    int node0 = blockIdx.x * 32;
    for (int i = tid; i < 32 * (DF / 4); i += 256) {
        int r = i >> 5, c = i & 31;
        ((float4*)&sx[r][0])[c] =
            ((const float4*)(x + (size_t)(node0 + r) * DF))[c];
    }
    __syncthreads();
    int warp = tid >> 5, lane = tid & 31;
    int nb = warp * 4;
    float acc0 = 0.f, acc1 = 0.f, acc2 = 0.f, acc3 = 0.f;
    const float4* wt = (const float4*)&sWt[lane][0];
    const float4* x0 = (const float4*)&sx[nb + 0][0];
    const float4* x1 = (const float4*)&sx[nb + 1][0];
    const float4* x2 = (const float4*)&sx[nb + 2][0];
    const float4* x3 = (const float4*)&sx[nb + 3][0];
#pragma unroll 8
    for (int q = 0; q < DF / 4; q++) {
        float4 w = wt[q];
        float4 a = x0[q], b = x1[q], c = x2[q], d = x3[q];
        acc0 += a.x * w.x + a.y * w.y + a.z * w.z + a.w * w.w;
        acc1 += b.x * w.x + b.y * w.y + b.z * w.z + b.w * w.w;
        acc2 += c.x * w.x + c.y * w.y + c.z * w.z + c.w * w.w;
        acc3 += d.x * w.x + d.y * w.y + d.z * w.z + d.w * w.w;
    }
    int n = node0 + nb;
    acc0 *= g_dinv[n + 0];
    acc1 *= g_dinv[n + 1];
    acc2 *= g_dinv[n + 2];
    acc3 *= g_dinv[n + 3];
    // pack adjacent feature columns into half2 (even lanes store)
    float o0 = __shfl_down_sync(~0u, acc0, 1);
    float o1 = __shfl_down_sync(~0u, acc1, 1);
    float o2 = __shfl_down_sync(~0u, acc2, 1);
    float o3 = __shfl_down_sync(~0u, acc3, 1);
    if ((lane & 1) == 0) {
        int h = lane >> 1;
        g_g1h[(n + 0) * (H1 / 2) + h] = __floats2half2_rn(acc0, o0);
        g_g1h[(n + 1) * (H1 / 2) + h] = __floats2half2_rn(acc1, o1);
        g_g1h[(n + 2) * (H1 / 2) + h] = __floats2half2_rn(acc2, o2);
        g_g1h[(n + 3) * (H1 / 2) + h] = __floats2half2_rn(acc3, o3);
    }
}

// ---- K6: gather layer-1 (fp16) + relu + W2 matvec + dinv -> g2 fp16 ----
// warp per node; half-warp per edge; lane handles feature pair fp
__global__ void k_gather_mid(const float* __restrict__ b1, const float* __restrict__ W2) {
    __shared__ float sW2[H1 * H2];
    __shared__ float su[8][H1 + 2];
    int tid = threadIdx.x;
    for (int i = tid; i < H1 * H2; i += 256) sW2[i] = W2[i];
    __syncthreads();
    int warp = tid >> 5, lane = tid & 31;
    int node = blockIdx.x * 8 + warp;       // NN % 8 == 0
    int sub = lane >> 4;                    // which edge of the pair
    int fp  = lane & 15;                    // feature-pair index
    int s = g_off[node], t = g_off[node + 1];
    float2 a0 = make_float2(0.f, 0.f), a1 = make_float2(0.f, 0.f);
    int e = s + sub;
    for (; e + 2 < t; e += 4) {
        int s0 = __ldg(&g_csr[e]);
        int s1 = __ldg(&g_csr[e + 2]);
        float2 v0 = __half22float2(g_g1h[s0 * (H1 / 2) + fp]);
        float2 v1 = __half22float2(g_g1h[s1 * (H1 / 2) + fp]);
        a0.x += v0.x; a0.y += v0.y;
        a1.x += v1.x; a1.y += v1.y;
    }
    for (; e < t; e += 2) {
        int s0 = __ldg(&g_csr[e]);
        float2 v0 = __half22float2(g_g1h[s0 * (H1 / 2) + fp]);
        a0.x += v0.x; a0.y += v0.y;
    }
    float ax = a0.x + a1.x, ay = a0.y + a1.y;
    // combine the two half-warps
    ax += __shfl_xor_sync(~0u, ax, 16);
    ay += __shfl_xor_sync(~0u, ay, 16);
    // self-loop + relu + bias (all lanes compute; halves duplicate)
    float2 sl = __half22float2(g_g1h[node * (H1 / 2) + fp]);
    float dinv = g_dinv[node];
    float ux = fmaxf(fmaf(ax + sl.x, dinv, __ldg(&b1[2 * fp])), 0.f);
    float uy = fmaxf(fmaf(ay + sl.y, dinv, __ldg(&b1[2 * fp + 1])), 0.f);
    if (sub == 0) {
        su[warp][2 * fp]     = ux;
        su[warp][2 * fp + 1] = uy;
    }
    __syncwarp();
    // matvec: output col = lane & 15 (lanes >=16 duplicate harmlessly)
    int col = lane & 15;
    float acc = 0.f;
#pragma unroll
    for (int k = 0; k < H1; k++)
        acc = fmaf(su[warp][k], sW2[k * H2 + col], acc);
    acc *= dinv;
    float nb = __shfl_down_sync(~0u, acc, 1);
    if (lane < 16 && (lane & 1) == 0)
        g_g2h[node * (H2 / 2) + (lane >> 1)] = __floats2half2_rn(acc, nb);
}

// ---- K7: gather layer-2 (fp16) -> agg2 fp32 (quarter-warp per edge) ----
__global__ void k_gather2() {
    int tid = threadIdx.x;
    int warp = tid >> 5, lane = tid & 31;
    int node = blockIdx.x * 8 + warp;
    int sub = lane >> 3;                    // 0..3
    int fp  = lane & 7;                     // feature-pair index
    int s = g_off[node], t = g_off[node + 1];
    float2 a0 = make_float2(0.f, 0.f), a1 = make_float2(0.f, 0.f);
    int e = s + sub;
    for (; e + 4 < t; e += 8) {
        int s0 = __ldg(&g_csr[e]);
        int s1 = __ldg(&g_csr[e + 4]);
        float2 v0 = __half22float2(g_g2h[s0 * (H2 / 2) + fp]);
        float2 v1 = __half22float2(g_g2h[s1 * (H2 / 2) + fp]);
        a0.x += v0.x; a0.y += v0.y;
        a1.x += v1.x; a1.y += v1.y;
    }
    for (; e < t; e += 4) {
        int s0 = __ldg(&g_csr[e]);
        float2 v0 = __half22float2(g_g2h[s0 * (H2 / 2) + fp]);
        a0.x += v0.x; a0.y += v0.y;
    }
    float ax = a0.x + a1.x, ay = a0.y + a1.y;
    ax += __shfl_xor_sync(~0u, ax, 8);
    ay += __shfl_xor_sync(~0u, ay, 8);
    ax += __shfl_xor_sync(~0u, ax, 16);
    ay += __shfl_xor_sync(~0u, ay, 16);
    if (sub == 0) {
        float2 sl = __half22float2(g_g2h[node * (H2 / 2) + fp]);
        ((float2*)g_agg2)[node * (H2 / 2) + fp] =
            make_float2(ax + sl.x, ay + sl.y);
    }
}

// ---- K8: relu(dinv*agg2 + b2) @ Wc + bc -> log_softmax -> out ----
__global__ void k_final(const float* __restrict__ b2, const float* __restrict__ Wc,
                        const float* __restrict__ bc, float* __restrict__ out) {
    int node = blockIdx.x * blockDim.x + threadIdx.x;
    if (node >= NN) return;
    float dinv = g_dinv[node];
    float u[H2];
    const float4* a = (const float4*)(g_agg2 + (size_t)node * H2);
#pragma unroll
    for (int q = 0; q < 4; q++) {
        float4 v = a[q];
        u[4 * q + 0] = v.x; u[4 * q + 1] = v.y;
        u[4 * q + 2] = v.z; u[4 * q + 3] = v.w;
    }
#pragma unroll
    for (int k = 0; k < H2; k++)
        u[k] = fmaxf(fmaf(u[k], dinv, __ldg(&b2[k])), 0.f);
    float l[NC];
#pragma unroll
    for (int j = 0; j < NC; j++) l[j] = __ldg(&bc[j]);
#pragma unroll
    for (int k = 0; k < H2; k++) {
        float uk = u[k];
#pragma unroll
        for (int j = 0; j < NC; j++)
            l[j] = fmaf(uk, __ldg(&Wc[k * NC + j]), l[j]);
    }
    float m = l[0];
#pragma unroll
    for (int j = 1; j < NC; j++) m = fmaxf(m, l[j]);
    float sum = 0.f;
#pragma unroll
    for (int j = 0; j < NC; j++) sum += expf(l[j] - m);
    float lse = m + logf(sum);
    float4* o = (float4*)(out + (size_t)node * NC);
    o[0] = make_float4(l[0] - lse, l[1] - lse, l[2] - lse, l[3] - lse);
    o[1] = make_float4(l[4] - lse, l[5] - lse, l[6] - lse, l[7] - lse);
}

extern "C" void kernel_launch(void* const* d_in, const int* in_sizes, int n_in,
                              void* d_out, int out_size) {
    (void)out_size;
    const float* x  = nullptr; const int* ei = nullptr;
    const float* W1 = nullptr; const float* b1 = nullptr;
    const float* W2 = nullptr; const float* b2 = nullptr;
    const float* Wc = nullptr; const float* bc = nullptr;
    for (int i = 0; i < n_in; i++) {
        switch (in_sizes[i]) {
            case NN * DF:    x  = (const float*)d_in[i]; break;  // 12,800,000
            case 2 * NE:     ei = (const int*)d_in[i];   break;  //  6,400,000
            case DF * H1:    W1 = (const float*)d_in[i]; break;  //      4,096
            case H1 * H2:    W2 = (const float*)d_in[i]; break;  //        512
            case H2 * NC:    Wc = (const float*)d_in[i]; break;  //        128
            case H1:         b1 = (const float*)d_in[i]; break;  //         32
            case H2:         b2 = (const float*)d_in[i]; break;  //         16
            case NC:         bc = (const float*)d_in[i]; break;  //          8
            default: break;
        }
    }
    float* out = (float*)d_out;

    k_init<<<NBLK, 256>>>();
    k_deg<<<NE / 256, 256>>>(ei);
    k_dinv<<<NBLK, 256>>>();
    k_scan_block<<<NBLK, 256>>>();
    k_scan_top<<<1, 512>>>();
    k_scan_add<<<NBLK, 256>>>();
    k_place<<<NE / 256, 256>>>(ei);
    k_gemm1<<<NN / 32, 256>>>(x, W1);       // 3125 blocks
    k_gather_mid<<<NN / 8, 256>>>(b1, W2);  // 12500 blocks
    k_gather2<<<NN / 8, 256>>>();
    k_final<<<NBLK, 256>>>(b2, Wc, bc, out);
}